// round 2
// baseline (speedup 1.0000x reference)
#include <cuda_runtime.h>
#include <math.h>

#define MEM_DIM 2000
#define FEA     256
#define NPIX    32768       // 32 * 32 * 32
#define HW      1024        // 32 * 32
#define ZSTRIDE 32768
#define SHRINK  0.0025f
#define CAP     64

#define BM 128
#define BJ 128
#define BK 16

// 262 MB scratch for z = q @ M^T, stored TRANSPOSED: z[j][n]
__device__ float g_z[(size_t)MEM_DIM * ZSTRIDE];

// ---------------------------------------------------------------------------
// Kernel 1: z[j][n] = sum_k q[n][k] * M[j][k]
//   q[n][k] = x[b*FEA*HW + k*HW + hw],  n = b*HW + hw
// Tiled SIMT fp32 GEMM, 128x128 tile, 8x8 per-thread microtile, 256 threads.
// ---------------------------------------------------------------------------
__global__ void __launch_bounds__(256, 2)
gemm1_kernel(const float* __restrict__ x, const float* __restrict__ Mm)
{
    __shared__ float As[BK][BM];        // [k][n]
    __shared__ float Bs[BK][BJ + 4];    // [k][j], padded

    const int n0 = blockIdx.x * BM;
    const int j0 = blockIdx.y * BJ;
    const int b   = n0 >> 10;
    const int hw0 = n0 & 1023;
    const float* xb = x + ((size_t)b * FEA) * HW + hw0;

    const int tid = threadIdx.x;
    const int tn = (tid & 15) << 3;   // n offset of this thread's 8-col chunk
    const int tj = (tid >> 4) << 3;   // j offset of this thread's 8-row chunk

    float acc[8][8];
#pragma unroll
    for (int i = 0; i < 8; i++)
#pragma unroll
        for (int jx = 0; jx < 8; jx++) acc[i][jx] = 0.f;

    for (int k0 = 0; k0 < FEA; k0 += BK) {
        // Load A tile: 2048 floats, coalesced along n
#pragma unroll
        for (int i = 0; i < 8; i++) {
            int idx = tid + i * 256;
            int kk = idx >> 7, nn = idx & 127;
            As[kk][nn] = xb[(size_t)(k0 + kk) * HW + nn];
        }
        // Load B tile: 2048 floats, 64B segments along k
#pragma unroll
        for (int i = 0; i < 8; i++) {
            int idx = tid + i * 256;
            int kk = idx & 15, jj = idx >> 4;
            int j = j0 + jj;
            Bs[kk][jj] = (j < MEM_DIM) ? Mm[(size_t)j * FEA + k0 + kk] : 0.f;
        }
        __syncthreads();

#pragma unroll
        for (int kk = 0; kk < BK; kk++) {
            float a[8], bb[8];
            *(float4*)(a)     = *(const float4*)&As[kk][tn];
            *(float4*)(a + 4) = *(const float4*)&As[kk][tn + 4];
            *(float4*)(bb)     = *(const float4*)&Bs[kk][tj];
            *(float4*)(bb + 4) = *(const float4*)&Bs[kk][tj + 4];
#pragma unroll
            for (int jj2 = 0; jj2 < 8; jj2++)
#pragma unroll
                for (int nn = 0; nn < 8; nn++)
                    acc[jj2][nn] = fmaf(a[nn], bb[jj2], acc[jj2][nn]);
        }
        __syncthreads();
    }

    // Epilogue: write z[j][n], coalesced along n
#pragma unroll
    for (int jj2 = 0; jj2 < 8; jj2++) {
        int j = j0 + tj + jj2;
        if (j < MEM_DIM) {
            float* zp = g_z + (size_t)j * ZSTRIDE + n0 + tn;
            *(float4*)(zp)     = *(float4*)&acc[jj2][0];
            *(float4*)(zp + 4) = *(float4*)&acc[jj2][4];
        }
    }
}

// ---------------------------------------------------------------------------
// Kernel 2: per 16-pixel block: softmax + hard-shrink + L1-renorm over 2000,
// transposed att_map write, sparse GEMM2 (survivor list) + transposed y write.
// smem: zs[2000][16] + reduce buffers + survivor lists + y tile.
// ---------------------------------------------------------------------------
#define SMEM_EPI ((MEM_DIM*16 + 256 + 16 + 16 + 16 + 16*CAP*2 + 16*256) * 4)

__global__ void __launch_bounds__(256)
epilogue_kernel(const float* __restrict__ Mm,
                float* __restrict__ y, float* __restrict__ att)
{
    extern __shared__ float sm[];
    float* zs     = sm;                       // [2000][16]
    float* red    = sm + MEM_DIM * 16;        // [16 groups][16 pixels]
    float* denomv = red + 256;                // 16: 1/denom per pixel
    int*   cnt    = (int*)(denomv + 16);      // 16
    int*   ovf    = cnt + 16;                 // 16
    int*   lj     = ovf + 16;                 // [16][CAP]
    float* lv     = (float*)(lj + 16 * CAP);  // [16][CAP]
    float* yt     = lv + 16 * CAP;            // [16][256]

    const int tid = threadIdx.x;
    const int n0  = blockIdx.x * 16;
    const int b   = n0 >> 10;
    const int hw0 = n0 & 1023;

    // Load z tile (coalesced 64B per j-row)
    for (int idx = tid; idx < MEM_DIM * 4; idx += 256) {
        int j = idx >> 2, q = (idx & 3) << 2;
        *(float4*)&zs[j * 16 + q] =
            *(const float4*)&g_z[(size_t)j * ZSTRIDE + n0 + q];
    }
    if (tid < 16) { cnt[tid] = 0; ovf[tid] = 0; }
    __syncthreads();

    const int p = tid & 15;    // pixel
    const int g = tid >> 4;    // group (j-stripe)

    // ---- Phase A: row max ----
    float mx = -1e30f;
    for (int j = g; j < MEM_DIM; j += 16) mx = fmaxf(mx, zs[j * 16 + p]);
    red[g * 16 + p] = mx;
    __syncthreads();
    for (int s = 8; s > 0; s >>= 1) {
        if (g < s) red[g * 16 + p] = fmaxf(red[g * 16 + p], red[(g + s) * 16 + p]);
        __syncthreads();
    }
    mx = red[p];
    __syncthreads();

    // ---- Phase B: softmax denominator S ----
    float sum = 0.f;
    for (int j = g; j < MEM_DIM; j += 16) sum += __expf(zs[j * 16 + p] - mx);
    red[g * 16 + p] = sum;
    __syncthreads();
    for (int s = 8; s > 0; s >>= 1) {
        if (g < s) red[g * 16 + p] += red[(g + s) * 16 + p];
        __syncthreads();
    }
    const float S = red[p];
    __syncthreads();
    const float invS = 1.f / S;

    // ---- Phase C: hard-shrink + L1 sum; record survivors ----
    float dsum = 0.f;
    for (int j = g; j < MEM_DIM; j += 16) {
        float z = zs[j * 16 + p];
        float w = __expf(z - mx) * invS;       // fast scan
        float s2 = 0.f;
        if (w > 0.999f * SHRINK) {
            // precise path near/above threshold (matches reference exp)
            float we = expf(z - mx) / S;
            float d = we - SHRINK;
            if (d > 0.f) {
                s2 = d * we / (d + 1e-12f);
                int id = atomicAdd(&cnt[p], 1);
                if (id < CAP) { lj[p * CAP + id] = j; lv[p * CAP + id] = s2; }
                else ovf[p] = 1;
            }
        }
        zs[j * 16 + p] = s2;
        dsum += s2;
    }
    red[g * 16 + p] = dsum;
    __syncthreads();
    for (int s = 8; s > 0; s >>= 1) {
        if (g < s) red[g * 16 + p] += red[(g + s) * 16 + p];
        __syncthreads();
    }
    if (tid < 16) denomv[tid] = 1.f / fmaxf(red[tid], 1e-12f);
    __syncthreads();

    // ---- Phase D: write att_map[b][j][h][w] (coalesced 64B per j) ----
    float* attb = att + ((size_t)b * MEM_DIM) * HW + hw0;
    for (int idx = tid; idx < MEM_DIM * 4; idx += 256) {
        int j = idx >> 2, q = (idx & 3) << 2;
        float4 v = *(float4*)&zs[j * 16 + q];
        v.x *= denomv[q];     v.y *= denomv[q + 1];
        v.z *= denomv[q + 2]; v.w *= denomv[q + 3];
        *(float4*)&attb[(size_t)j * HW + q] = v;
    }

    // ---- Phase E: sparse GEMM2 -> y tile ----
    for (int idx = tid; idx < 16 * 256; idx += 256) yt[idx] = 0.f;
    __syncthreads();

    const int wid = tid >> 5, lane = tid & 31;
    for (int pp = wid; pp < 16; pp += 8) {
        if (ovf[pp]) continue;
        int nc = cnt[pp];
        float idn = denomv[pp];
        float acc[8] = {0, 0, 0, 0, 0, 0, 0, 0};
        for (int i = 0; i < nc; i++) {
            int jv = lj[pp * CAP + i];
            float a = lv[pp * CAP + i] * idn;
            const float* mr = Mm + (size_t)jv * FEA;
#pragma unroll
            for (int r = 0; r < 8; r++)
                acc[r] = fmaf(a, mr[r * 32 + lane], acc[r]);
        }
#pragma unroll
        for (int r = 0; r < 8; r++) yt[pp * 256 + r * 32 + lane] = acc[r];
    }
    __syncthreads();

    // Dense fallback for (statistically impossible) survivor-list overflow
    for (int pp = 0; pp < 16; pp++) {
        if (!ovf[pp]) continue;
        float acc = 0.f;
        int c = tid;
        for (int j = 0; j < MEM_DIM; j++)
            acc = fmaf(zs[j * 16 + pp], Mm[(size_t)j * FEA + c], acc);
        yt[pp * 256 + c] = acc * denomv[pp];
    }
    __syncthreads();

    // ---- Write y[b][c][h][w] (coalesced 64B per c) ----
    float* yb = y + ((size_t)b * FEA) * HW + hw0;
    for (int idx = tid; idx < 16 * 256; idx += 256) {
        int c = idx >> 4, pp = idx & 15;
        yb[(size_t)c * HW + pp] = yt[pp * 256 + c];
    }
}

// ---------------------------------------------------------------------------
extern "C" void kernel_launch(void* const* d_in, const int* in_sizes, int n_in,
                              void* d_out, int out_size)
{
    const float* x  = (const float*)d_in[0];
    const float* Mm = (const float*)d_in[1];
    // defensive: detect swapped input order by element count
    if (in_sizes[0] == MEM_DIM * FEA && in_sizes[1] == NPIX * FEA) {
        const float* t = x; x = Mm; Mm = t;
    }

    float* y   = (float*)d_out;
    float* att = (float*)d_out + (size_t)32 * FEA * HW;   // y is 8388608 floats

    dim3 g1(NPIX / BM, (MEM_DIM + BJ - 1) / BJ);
    gemm1_kernel<<<g1, 256>>>(x, Mm);

    cudaFuncSetAttribute(epilogue_kernel,
                         cudaFuncAttributeMaxDynamicSharedMemorySize, SMEM_EPI);
    epilogue_kernel<<<NPIX / 16, 256, SMEM_EPI>>>(Mm, y, att);
}